// round 14
// baseline (speedup 1.0000x reference)
#include <cuda_runtime.h>
#include <cuda_fp16.h>

#define N_NODES 50000
#define N_EDGES 800000
#define HDIM    64
#define NCLS    6
#define NGRAPH  500
#define BN_EPS  1e-5f
#define CAP     64   // per-node edge bucket capacity (max in-degree ~45)

// ---------------- scratch (allocation-free: __device__ globals) -------------
// Cross-call state returns to zero by the END of each call (pool/fc);
// first call rides .bss zero-init.
__device__ __align__(16) __half d_th[N_NODES * HDIM];   // dinv-scaled post-GEMM features (fp16)
__device__ __align__(16) __half d_agg[N_NODES * HDIM];  // aggregated features (fp16)
__device__ int   d_pos[N_NODES];              // bucket cursors == in-degree counts
__device__ __align__(16) int d_csr_i[N_NODES * CAP];  // per-node src-index buckets
__device__ float d_sumA[3 * HDIM];            // per-layer BN sum
__device__ float d_sqA[3 * HDIM];             // per-layer BN sumsq
__device__ __align__(16) float d_pool[NGRAPH * HDIM];
__device__ float d_gcnt[NGRAPH];

// ---------------- bucket scatter ------------------------------------------------
__global__ void k_scatter(const int* __restrict__ src, const int* __restrict__ dst) {
    int e = (blockIdx.x * blockDim.x + threadIdx.x) * 4;
    if (e >= N_EDGES) return;
    int4 s4 = *(const int4*)(src + e);
    int4 d4 = *(const int4*)(dst + e);
    int p0 = atomicAdd(&d_pos[d4.x], 1);
    int p1 = atomicAdd(&d_pos[d4.y], 1);
    int p2 = atomicAdd(&d_pos[d4.z], 1);
    int p3 = atomicAdd(&d_pos[d4.w], 1);
    if (p0 < CAP) d_csr_i[d4.x * CAP + p0] = s4.x;
    if (p1 < CAP) d_csr_i[d4.y * CAP + p1] = s4.y;
    if (p2 < CAP) d_csr_i[d4.z * CAP + p2] = s4.z;
    if (p3 < CAP) d_csr_i[d4.w * CAP + p3] = s4.w;
}

// ---------------- tensor-core GEMM ---------------------------------------------
// th'[row] = dinv[row] * (act(X)[row] @ W), fp16 store.
// 64-row tile, 256 threads = 8 warps: warp w -> rows (w&3)*16, cols (w>>2)*32.
__global__ __launch_bounds__(256) void k_gemm(const float* __restrict__ Xext,
                                              const float* __restrict__ W,
                                              const float* __restrict__ gp,
                                              const float* __restrict__ bep,
                                              const float* __restrict__ bp,
                                              int layer) {
    __shared__ __half Xs[64][72];    // 144B row stride: conflict-free ldmatrix
    __shared__ __half Wsh[64][72];
    __shared__ __align__(16) float sh_a[64], sh_c[64];

    const int apply_bn = layer > 0;
    int tid = threadIdx.x;
    int base = blockIdx.x * 64;

    if (apply_bn && tid < 64) {
        int o = (layer - 1) * 64 + tid;
        float mu  = d_sumA[o] * (1.0f / N_NODES);
        float var = d_sqA[o] * (1.0f / N_NODES) - mu * mu;
        float inv = rsqrtf(var + BN_EPS);
        float a = __ldg(gp + tid) * inv;
        sh_a[tid] = a;
        sh_c[tid] = __ldg(bep + tid) + a * (__ldg(bp + tid) - mu);
    }

    // stage W[k][n] -> fp16 shared
    {
        int k = tid >> 4, cg = tid & 15;
#pragma unroll
        for (int i = 0; i < 4; i++) {
            float4 w = ((const float4*)W)[(k + i * 16) * 16 + cg];
            __half2 h0 = __floats2half2_rn(w.x, w.y);
            __half2 h1 = __floats2half2_rn(w.z, w.w);
            uint2 pk;
            pk.x = *(unsigned int*)&h0;
            pk.y = *(unsigned int*)&h1;
            *(uint2*)&Wsh[k + i * 16][cg * 4] = pk;
        }
    }
    __syncthreads();  // sh_a/sh_c ready before X staging uses them

    // stage X tile -> fp16 shared (layer 0: fp32 ext; layers 1,2: fp16 d_agg + BN)
    {
        int rl = tid >> 4, cg = tid & 15;
        float4 a4 = make_float4(0.f, 0.f, 0.f, 0.f);
        float4 c4 = make_float4(0.f, 0.f, 0.f, 0.f);
        if (apply_bn) {
            a4 = *(const float4*)&sh_a[cg * 4];
            c4 = *(const float4*)&sh_c[cg * 4];
        }
#pragma unroll
        for (int i = 0; i < 4; i++) {
            int row = base + rl + i * 16;
            float4 v = make_float4(0.f, 0.f, 0.f, 0.f);
            if (row < N_NODES) {
                if (apply_bn) {
                    uint2 pk = ((const uint2*)d_agg)[row * 16 + cg];
                    float2 lo = __half22float2(*(__half2*)&pk.x);
                    float2 hi = __half22float2(*(__half2*)&pk.y);
                    v = make_float4(lo.x, lo.y, hi.x, hi.y);
                    v.x = fmaxf(0.0f, fmaf(v.x, a4.x, c4.x));
                    v.y = fmaxf(0.0f, fmaf(v.y, a4.y, c4.y));
                    v.z = fmaxf(0.0f, fmaf(v.z, a4.z, c4.z));
                    v.w = fmaxf(0.0f, fmaf(v.w, a4.w, c4.w));
                } else {
                    v = ((const float4*)Xext)[row * 16 + cg];
                }
            }
            __half2 h0 = __floats2half2_rn(v.x, v.y);
            __half2 h1 = __floats2half2_rn(v.z, v.w);
            uint2 pk;
            pk.x = *(unsigned int*)&h0;
            pk.y = *(unsigned int*)&h1;
            *(uint2*)&Xs[rl + i * 16][cg * 4] = pk;
        }
    }
    __syncthreads();

    int w = tid >> 5, lane = tid & 31;
    int row0 = (w & 3) * 16;      // row strip
    int ncol0 = (w >> 2) * 32;    // column half

    float c[4][4];
#pragma unroll
    for (int n = 0; n < 4; n++)
#pragma unroll
        for (int j = 0; j < 4; j++) c[n][j] = 0.0f;

#pragma unroll
    for (int kc = 0; kc < 4; kc++) {
        unsigned int a0, a1, a2, a3;
        {
            const __half* p = &Xs[row0 + (lane & 15)][kc * 16 + (lane >> 4) * 8];
            unsigned int addr = (unsigned int)__cvta_generic_to_shared(p);
            asm volatile("ldmatrix.sync.aligned.m8n8.x4.shared.b16 {%0,%1,%2,%3}, [%4];"
                         : "=r"(a0), "=r"(a1), "=r"(a2), "=r"(a3) : "r"(addr));
        }
#pragma unroll
        for (int np = 0; np < 2; np++) {
            unsigned int b0, b1, b2, b3;
            const __half* p = &Wsh[kc * 16 + (lane & 15)][ncol0 + np * 16 + (lane >> 4) * 8];
            unsigned int addr = (unsigned int)__cvta_generic_to_shared(p);
            asm volatile("ldmatrix.sync.aligned.m8n8.x4.trans.shared.b16 {%0,%1,%2,%3}, [%4];"
                         : "=r"(b0), "=r"(b1), "=r"(b2), "=r"(b3) : "r"(addr));
            int nt0 = np * 2, nt1 = np * 2 + 1;
            asm volatile("mma.sync.aligned.m16n8k16.row.col.f32.f16.f16.f32 "
                         "{%0,%1,%2,%3}, {%4,%5,%6,%7}, {%8,%9}, {%0,%1,%2,%3};"
                         : "+f"(c[nt0][0]), "+f"(c[nt0][1]), "+f"(c[nt0][2]), "+f"(c[nt0][3])
                         : "r"(a0), "r"(a1), "r"(a2), "r"(a3), "r"(b0), "r"(b1));
            asm volatile("mma.sync.aligned.m16n8k16.row.col.f32.f16.f16.f32 "
                         "{%0,%1,%2,%3}, {%4,%5,%6,%7}, {%8,%9}, {%0,%1,%2,%3};"
                         : "+f"(c[nt1][0]), "+f"(c[nt1][1]), "+f"(c[nt1][2]), "+f"(c[nt1][3])
                         : "r"(a0), "r"(a1), "r"(a2), "r"(a3), "r"(b2), "r"(b3));
        }
    }

    // epilogue: scale rows by dinv = rsqrt(deg+1), convert to fp16, store
    int r0 = base + row0 + (lane >> 2);
    int r1 = r0 + 8;
    bool ok0 = r0 < N_NODES, ok1 = r1 < N_NODES;
    float dv0 = ok0 ? rsqrtf((float)d_pos[r0] + 1.0f) : 0.0f;
    float dv1 = ok1 ? rsqrtf((float)d_pos[r1] + 1.0f) : 0.0f;
#pragma unroll
    for (int nt = 0; nt < 4; nt++) {
        int col = ncol0 + nt * 8 + (lane & 3) * 2;
        if (ok0) {
            __half2 h = __floats2half2_rn(c[nt][0] * dv0, c[nt][1] * dv0);
            *(__half2*)&d_th[r0 * 64 + col] = h;
        }
        if (ok1) {
            __half2 h = __floats2half2_rn(c[nt][2] * dv1, c[nt][3] * dv1);
            *(__half2*)&d_th[r1 * 64 + col] = h;
        }
    }
}

// ---------------- bucket pull aggregation + fused BN stats ---------------------
// agg[d] = dinv[d] * (th'[d] + sum th'[s]); weight-free.
// 2 nodes per warp: each half-warp (16 lanes) owns one node; each lane owns
// 4 columns via one uint2 (8B) gather -> half the gather instructions, double
// the independent edge streams per warp. 16 nodes per warp total.
__device__ __forceinline__ float4 hx_cvt(uint2 pk) {
    float2 lo = __half22float2(*(__half2*)&pk.x);
    float2 hi = __half22float2(*(__half2*)&pk.y);
    return make_float4(lo.x, lo.y, hi.x, hi.y);
}

__global__ __launch_bounds__(256) void k_aggregate(const float* __restrict__ b,
                                                   int layer) {
    int tid = threadIdx.x;
    int wid = tid >> 5;
    int lane = tid & 31;
    int sub = lane >> 4;      // which node of the pair
    int sl  = lane & 15;      // uint2 slot = 4 columns
    int node0 = (blockIdx.x * 8 + wid) * 16;   // 16 nodes per warp

    __shared__ float sh_s[64], sh_q[64];
    if (tid < 64) { sh_s[tid] = 0.0f; sh_q[tid] = 0.0f; }

    float4 bb = *(const float4*)(b + sl * 4);
    float4 ssum = make_float4(0.f, 0.f, 0.f, 0.f);
    float4 ssq  = make_float4(0.f, 0.f, 0.f, 0.f);

    const uint2* t2 = (const uint2*)d_th;   // row = 16 uint2 (128B)

#pragma unroll 1
    for (int p = 0; p < 8; p++) {
        int node = node0 + p * 2 + sub;
        if (node >= N_NODES) break;          // N even: both halves exit together
        int cnt = d_pos[node];
        float dv = rsqrtf((float)(cnt + 1));
        const int4* bkt4 = (const int4*)&d_csr_i[node * CAP];

        float4 a0 = hx_cvt(__ldg(&t2[node * 16 + sl]));   // self (th'[d])
        float4 a1 = make_float4(0.f, 0.f, 0.f, 0.f);
        float4 a2 = make_float4(0.f, 0.f, 0.f, 0.f);
        float4 a3 = make_float4(0.f, 0.f, 0.f, 0.f);

        int j = 0;
        // 8-edge groups: 2 int4 index loads, 8 independent uint2 gathers
        for (; j + 8 <= cnt; j += 8) {
            int4 ia = __ldg(bkt4 + (j >> 2));
            int4 ib = __ldg(bkt4 + (j >> 2) + 1);
            float4 v0 = hx_cvt(__ldg(&t2[ia.x * 16 + sl]));
            float4 v1 = hx_cvt(__ldg(&t2[ia.y * 16 + sl]));
            float4 v2 = hx_cvt(__ldg(&t2[ia.z * 16 + sl]));
            float4 v3 = hx_cvt(__ldg(&t2[ia.w * 16 + sl]));
            float4 v4 = hx_cvt(__ldg(&t2[ib.x * 16 + sl]));
            float4 v5 = hx_cvt(__ldg(&t2[ib.y * 16 + sl]));
            float4 v6 = hx_cvt(__ldg(&t2[ib.z * 16 + sl]));
            float4 v7 = hx_cvt(__ldg(&t2[ib.w * 16 + sl]));
            a0.x += v0.x + v4.x; a0.y += v0.y + v4.y; a0.z += v0.z + v4.z; a0.w += v0.w + v4.w;
            a1.x += v1.x + v5.x; a1.y += v1.y + v5.y; a1.z += v1.z + v5.z; a1.w += v1.w + v5.w;
            a2.x += v2.x + v6.x; a2.y += v2.y + v6.y; a2.z += v2.z + v6.z; a2.w += v2.w + v6.w;
            a3.x += v3.x + v7.x; a3.y += v3.y + v7.y; a3.z += v3.z + v7.z; a3.w += v3.w + v7.w;
        }
        if (j + 4 <= cnt) {
            int4 ia = __ldg(bkt4 + (j >> 2));
            float4 v0 = hx_cvt(__ldg(&t2[ia.x * 16 + sl]));
            float4 v1 = hx_cvt(__ldg(&t2[ia.y * 16 + sl]));
            float4 v2 = hx_cvt(__ldg(&t2[ia.z * 16 + sl]));
            float4 v3 = hx_cvt(__ldg(&t2[ia.w * 16 + sl]));
            a0.x += v0.x; a0.y += v0.y; a0.z += v0.z; a0.w += v0.w;
            a1.x += v1.x; a1.y += v1.y; a1.z += v1.z; a1.w += v1.w;
            a2.x += v2.x; a2.y += v2.y; a2.z += v2.z; a2.w += v2.w;
            a3.x += v3.x; a3.y += v3.y; a3.z += v3.z; a3.w += v3.w;
            j += 4;
        }
        if (j < cnt) {
            int4 ia = __ldg(bkt4 + (j >> 2));
            int rem = cnt - j;
            float4 v0 = hx_cvt(__ldg(&t2[ia.x * 16 + sl]));
            a0.x += v0.x; a0.y += v0.y; a0.z += v0.z; a0.w += v0.w;
            if (rem > 1) {
                float4 v1 = hx_cvt(__ldg(&t2[ia.y * 16 + sl]));
                a1.x += v1.x; a1.y += v1.y; a1.z += v1.z; a1.w += v1.w;
            }
            if (rem > 2) {
                float4 v2 = hx_cvt(__ldg(&t2[ia.z * 16 + sl]));
                a2.x += v2.x; a2.y += v2.y; a2.z += v2.z; a2.w += v2.w;
            }
        }
        float4 acc;
        acc.x = dv * ((a0.x + a1.x) + (a2.x + a3.x));
        acc.y = dv * ((a0.y + a1.y) + (a2.y + a3.y));
        acc.z = dv * ((a0.z + a1.z) + (a2.z + a3.z));
        acc.w = dv * ((a0.w + a1.w) + (a2.w + a3.w));

        __half2 h0 = __floats2half2_rn(acc.x, acc.y);
        __half2 h1 = __floats2half2_rn(acc.z, acc.w);
        uint2 pk;
        pk.x = *(unsigned int*)&h0;
        pk.y = *(unsigned int*)&h1;
        ((uint2*)d_agg)[node * 16 + sl] = pk;

        float vx = acc.x + bb.x, vy = acc.y + bb.y;
        float vz = acc.z + bb.z, vw = acc.w + bb.w;
        ssum.x += vx; ssum.y += vy; ssum.z += vz; ssum.w += vw;
        ssq.x += vx * vx; ssq.y += vy * vy; ssq.z += vz * vz; ssq.w += vw * vw;
    }

    __syncthreads();
    atomicAdd(&sh_s[sl * 4 + 0], ssum.x);
    atomicAdd(&sh_s[sl * 4 + 1], ssum.y);
    atomicAdd(&sh_s[sl * 4 + 2], ssum.z);
    atomicAdd(&sh_s[sl * 4 + 3], ssum.w);
    atomicAdd(&sh_q[sl * 4 + 0], ssq.x);
    atomicAdd(&sh_q[sl * 4 + 1], ssq.y);
    atomicAdd(&sh_q[sl * 4 + 2], ssq.z);
    atomicAdd(&sh_q[sl * 4 + 3], ssq.w);
    __syncthreads();
    if (tid < 64) {
        atomicAdd(&d_sumA[layer * 64 + tid], sh_s[tid]);
        atomicAdd(&d_sqA[layer * 64 + tid], sh_q[tid]);
    }
}

// ---------------- pooling (fused BN+ReLU of layer 3) + classifier -------------
// Also resets d_pos to 0 for the NEXT call.
__global__ __launch_bounds__(256) void k_pool(const int* __restrict__ batch,
                                              const float* __restrict__ gp,
                                              const float* __restrict__ bep,
                                              const float* __restrict__ bp) {
    __shared__ __align__(16) float sh_a[64], sh_c[64];
    int tid = threadIdx.x;
    if (tid < 64) {
        int o = 2 * 64 + tid;
        float mu  = d_sumA[o] * (1.0f / N_NODES);
        float var = d_sqA[o] * (1.0f / N_NODES) - mu * mu;
        float inv = rsqrtf(var + BN_EPS);
        float a = __ldg(gp + tid) * inv;
        sh_a[tid] = a;
        sh_c[tid] = __ldg(bep + tid) + a * (__ldg(bp + tid) - mu);
    }
    __syncthreads();

    int i = blockIdx.x * blockDim.x + tid;   // N*16 chunks (4 cols each)
    if (i >= N_NODES * 16) return;
    int node = i >> 4, c = i & 15;
    int g = __ldg(batch + node);
    float4 a4 = *(const float4*)&sh_a[c * 4];
    float4 c4 = *(const float4*)&sh_c[c * 4];
    uint2 pk = ((const uint2*)d_agg)[i];
    float2 lo = __half22float2(*(__half2*)&pk.x);
    float2 hi = __half22float2(*(__half2*)&pk.y);
    float4 v = make_float4(lo.x, lo.y, hi.x, hi.y);
    v.x = fmaxf(0.0f, fmaf(v.x, a4.x, c4.x));
    v.y = fmaxf(0.0f, fmaf(v.y, a4.y, c4.y));
    v.z = fmaxf(0.0f, fmaf(v.z, a4.z, c4.z));
    v.w = fmaxf(0.0f, fmaf(v.w, a4.w, c4.w));
    float* p = d_pool + (g * 64 + c * 4);
    asm volatile("red.global.add.v4.f32 [%0], {%1,%2,%3,%4};"
                 :: "l"(p), "f"(v.x), "f"(v.y), "f"(v.z), "f"(v.w)
                 : "memory");
    if (c == 0) {
        atomicAdd(&d_gcnt[g], 1.0f);
        d_pos[node] = 0;                 // reset cursor for next execution
    }
}

// fc; also zeroes pool/gcnt/BN stats for the next execution.
__global__ __launch_bounds__(64) void k_fc(const float* __restrict__ fcW,
                                           const float* __restrict__ fcb,
                                           float* __restrict__ out) {
    int g = blockIdx.x;
    int tid = threadIdx.x;  // 64
    __shared__ float p[64];
    float cnt = fmaxf(d_gcnt[g], 1.0f);
    p[tid] = d_pool[g * 64 + tid] / cnt;
    __syncthreads();

    d_pool[g * 64 + tid] = 0.0f;
    if (tid == 0) d_gcnt[g] = 0.0f;
    if (g == 0) {
#pragma unroll
        for (int l = 0; l < 3; l++) {
            d_sumA[l * 64 + tid] = 0.0f;
            d_sqA[l * 64 + tid] = 0.0f;
        }
    }

    if (tid < NCLS) {
        float acc = __ldg(fcb + tid);
#pragma unroll
        for (int k = 0; k < 64; k++)
            acc = fmaf(p[k], __ldg(fcW + k * NCLS + tid), acc);
        out[g * NCLS + tid] = acc;
    }
}

// ---------------- launch ------------------------------------------------------
extern "C" void kernel_launch(void* const* d_in, const int* in_sizes, int n_in,
                              void* d_out, int out_size) {
    const float* x     = (const float*)d_in[0];
    const int*   ei    = (const int*)d_in[1];
    const int*   src   = ei;              // edge_index[0]
    const int*   dst   = ei + N_EDGES;    // edge_index[1]
    const int*   batch = (const int*)d_in[2];
    const float* W[3]  = { (const float*)d_in[3],  (const float*)d_in[7],  (const float*)d_in[11] };
    const float* b[3]  = { (const float*)d_in[4],  (const float*)d_in[8],  (const float*)d_in[12] };
    const float* g[3]  = { (const float*)d_in[5],  (const float*)d_in[9],  (const float*)d_in[13] };
    const float* be[3] = { (const float*)d_in[6],  (const float*)d_in[10], (const float*)d_in[14] };
    const float* fcW   = (const float*)d_in[15];
    const float* fcb   = (const float*)d_in[16];
    float* out = (float*)d_out;

    const int gemm_grid = (N_NODES + 63) / 64;
    const int agg_grid = (N_NODES + 8 * 16 - 1) / (8 * 16);   // 16 nodes/warp

    // bucket CSR build (d_pos arrives zeroed: .bss / prev pool)
    k_scatter<<<(N_EDGES / 4 + 255) / 256, 256>>>(src, dst);

    for (int l = 0; l < 3; l++) {
        const float* gp  = l > 0 ? g[l - 1]  : g[0];
        const float* bep = l > 0 ? be[l - 1] : be[0];
        const float* bp  = l > 0 ? b[l - 1]  : b[0];
        k_gemm<<<gemm_grid, 256>>>(x, W[l], gp, bep, bp, l);
        k_aggregate<<<agg_grid, 256>>>(b[l], l);
    }

    k_pool<<<(N_NODES * 16 + 255) / 256, 256>>>(batch, g[2], be[2], b[2]);
    k_fc<<<NGRAPH, 64>>>(fcW, fcb, out);
}

// round 15
// speedup vs baseline: 1.3762x; 1.3762x over previous
#include <cuda_runtime.h>
#include <cuda_fp16.h>

#define N_NODES 50000
#define N_EDGES 800000
#define HDIM    64
#define NCLS    6
#define NGRAPH  500
#define BN_EPS  1e-5f
#define CAP     64   // per-node edge bucket capacity (max in-degree ~45)
#define NPW     8    // nodes per warp in aggregation

// ---------------- scratch (allocation-free: __device__ globals) -------------
// Cross-call state returns to zero by the END of each call (pool/fc);
// first call rides .bss zero-init.
__device__ __align__(16) __half d_th[N_NODES * HDIM];   // dinv-scaled post-GEMM features (fp16)
__device__ __align__(16) __half d_agg[N_NODES * HDIM];  // aggregated features (fp16)
__device__ int   d_pos[N_NODES];              // bucket cursors == in-degree counts
__device__ __align__(16) int d_csr_i[N_NODES * CAP];  // per-node src-index buckets
__device__ float d_sumA[3 * HDIM];            // per-layer BN sum
__device__ float d_sqA[3 * HDIM];             // per-layer BN sumsq
__device__ __align__(16) float d_pool[NGRAPH * HDIM];
__device__ float d_gcnt[NGRAPH];

// ---------------- bucket scatter ------------------------------------------------
__global__ void k_scatter(const int* __restrict__ src, const int* __restrict__ dst) {
    int e = (blockIdx.x * blockDim.x + threadIdx.x) * 4;
    if (e >= N_EDGES) return;
    int4 s4 = *(const int4*)(src + e);
    int4 d4 = *(const int4*)(dst + e);
    int p0 = atomicAdd(&d_pos[d4.x], 1);
    int p1 = atomicAdd(&d_pos[d4.y], 1);
    int p2 = atomicAdd(&d_pos[d4.z], 1);
    int p3 = atomicAdd(&d_pos[d4.w], 1);
    if (p0 < CAP) d_csr_i[d4.x * CAP + p0] = s4.x;
    if (p1 < CAP) d_csr_i[d4.y * CAP + p1] = s4.y;
    if (p2 < CAP) d_csr_i[d4.z * CAP + p2] = s4.z;
    if (p3 < CAP) d_csr_i[d4.w * CAP + p3] = s4.w;
}

// ---------------- tensor-core GEMM ---------------------------------------------
// th'[row] = dinv[row] * (act(X)[row] @ W), fp16 store.
// 64-row tile, 256 threads = 8 warps: warp w -> rows (w&3)*16, cols (w>>2)*32.
__global__ __launch_bounds__(256) void k_gemm(const float* __restrict__ Xext,
                                              const float* __restrict__ W,
                                              const float* __restrict__ gp,
                                              const float* __restrict__ bep,
                                              const float* __restrict__ bp,
                                              int layer) {
    __shared__ __half Xs[64][72];    // 144B row stride: conflict-free ldmatrix
    __shared__ __half Wsh[64][72];
    __shared__ __align__(16) float sh_a[64], sh_c[64];

    const int apply_bn = layer > 0;
    int tid = threadIdx.x;
    int base = blockIdx.x * 64;

    if (apply_bn && tid < 64) {
        int o = (layer - 1) * 64 + tid;
        float mu  = d_sumA[o] * (1.0f / N_NODES);
        float var = d_sqA[o] * (1.0f / N_NODES) - mu * mu;
        float inv = rsqrtf(var + BN_EPS);
        float a = __ldg(gp + tid) * inv;
        sh_a[tid] = a;
        sh_c[tid] = __ldg(bep + tid) + a * (__ldg(bp + tid) - mu);
    }

    // stage W[k][n] -> fp16 shared
    {
        int k = tid >> 4, cg = tid & 15;
#pragma unroll
        for (int i = 0; i < 4; i++) {
            float4 w = ((const float4*)W)[(k + i * 16) * 16 + cg];
            __half2 h0 = __floats2half2_rn(w.x, w.y);
            __half2 h1 = __floats2half2_rn(w.z, w.w);
            uint2 pk;
            pk.x = *(unsigned int*)&h0;
            pk.y = *(unsigned int*)&h1;
            *(uint2*)&Wsh[k + i * 16][cg * 4] = pk;
        }
    }
    __syncthreads();  // sh_a/sh_c ready before X staging uses them

    // stage X tile -> fp16 shared (layer 0: fp32 ext; layers 1,2: fp16 d_agg + BN)
    {
        int rl = tid >> 4, cg = tid & 15;
        float4 a4 = make_float4(0.f, 0.f, 0.f, 0.f);
        float4 c4 = make_float4(0.f, 0.f, 0.f, 0.f);
        if (apply_bn) {
            a4 = *(const float4*)&sh_a[cg * 4];
            c4 = *(const float4*)&sh_c[cg * 4];
        }
#pragma unroll
        for (int i = 0; i < 4; i++) {
            int row = base + rl + i * 16;
            float4 v = make_float4(0.f, 0.f, 0.f, 0.f);
            if (row < N_NODES) {
                if (apply_bn) {
                    uint2 pk = ((const uint2*)d_agg)[row * 16 + cg];
                    float2 lo = __half22float2(*(__half2*)&pk.x);
                    float2 hi = __half22float2(*(__half2*)&pk.y);
                    v = make_float4(lo.x, lo.y, hi.x, hi.y);
                    v.x = fmaxf(0.0f, fmaf(v.x, a4.x, c4.x));
                    v.y = fmaxf(0.0f, fmaf(v.y, a4.y, c4.y));
                    v.z = fmaxf(0.0f, fmaf(v.z, a4.z, c4.z));
                    v.w = fmaxf(0.0f, fmaf(v.w, a4.w, c4.w));
                } else {
                    v = ((const float4*)Xext)[row * 16 + cg];
                }
            }
            __half2 h0 = __floats2half2_rn(v.x, v.y);
            __half2 h1 = __floats2half2_rn(v.z, v.w);
            uint2 pk;
            pk.x = *(unsigned int*)&h0;
            pk.y = *(unsigned int*)&h1;
            *(uint2*)&Xs[rl + i * 16][cg * 4] = pk;
        }
    }
    __syncthreads();

    int w = tid >> 5, lane = tid & 31;
    int row0 = (w & 3) * 16;      // row strip
    int ncol0 = (w >> 2) * 32;    // column half

    float c[4][4];
#pragma unroll
    for (int n = 0; n < 4; n++)
#pragma unroll
        for (int j = 0; j < 4; j++) c[n][j] = 0.0f;

#pragma unroll
    for (int kc = 0; kc < 4; kc++) {
        unsigned int a0, a1, a2, a3;
        {
            const __half* p = &Xs[row0 + (lane & 15)][kc * 16 + (lane >> 4) * 8];
            unsigned int addr = (unsigned int)__cvta_generic_to_shared(p);
            asm volatile("ldmatrix.sync.aligned.m8n8.x4.shared.b16 {%0,%1,%2,%3}, [%4];"
                         : "=r"(a0), "=r"(a1), "=r"(a2), "=r"(a3) : "r"(addr));
        }
#pragma unroll
        for (int np = 0; np < 2; np++) {
            unsigned int b0, b1, b2, b3;
            const __half* p = &Wsh[kc * 16 + (lane & 15)][ncol0 + np * 16 + (lane >> 4) * 8];
            unsigned int addr = (unsigned int)__cvta_generic_to_shared(p);
            asm volatile("ldmatrix.sync.aligned.m8n8.x4.trans.shared.b16 {%0,%1,%2,%3}, [%4];"
                         : "=r"(b0), "=r"(b1), "=r"(b2), "=r"(b3) : "r"(addr));
            int nt0 = np * 2, nt1 = np * 2 + 1;
            asm volatile("mma.sync.aligned.m16n8k16.row.col.f32.f16.f16.f32 "
                         "{%0,%1,%2,%3}, {%4,%5,%6,%7}, {%8,%9}, {%0,%1,%2,%3};"
                         : "+f"(c[nt0][0]), "+f"(c[nt0][1]), "+f"(c[nt0][2]), "+f"(c[nt0][3])
                         : "r"(a0), "r"(a1), "r"(a2), "r"(a3), "r"(b0), "r"(b1));
            asm volatile("mma.sync.aligned.m16n8k16.row.col.f32.f16.f16.f32 "
                         "{%0,%1,%2,%3}, {%4,%5,%6,%7}, {%8,%9}, {%0,%1,%2,%3};"
                         : "+f"(c[nt1][0]), "+f"(c[nt1][1]), "+f"(c[nt1][2]), "+f"(c[nt1][3])
                         : "r"(a0), "r"(a1), "r"(a2), "r"(a3), "r"(b2), "r"(b3));
        }
    }

    // epilogue: scale rows by dinv = rsqrt(deg+1), convert to fp16, store
    int r0 = base + row0 + (lane >> 2);
    int r1 = r0 + 8;
    bool ok0 = r0 < N_NODES, ok1 = r1 < N_NODES;
    float dv0 = ok0 ? rsqrtf((float)d_pos[r0] + 1.0f) : 0.0f;
    float dv1 = ok1 ? rsqrtf((float)d_pos[r1] + 1.0f) : 0.0f;
#pragma unroll
    for (int nt = 0; nt < 4; nt++) {
        int col = ncol0 + nt * 8 + (lane & 3) * 2;
        if (ok0) {
            __half2 h = __floats2half2_rn(c[nt][0] * dv0, c[nt][1] * dv0);
            *(__half2*)&d_th[r0 * 64 + col] = h;
        }
        if (ok1) {
            __half2 h = __floats2half2_rn(c[nt][2] * dv1, c[nt][3] * dv1);
            *(__half2*)&d_th[r1 * 64 + col] = h;
        }
    }
}

// ---------------- bucket pull aggregation + fused BN stats ---------------------
// agg[d] = dinv[d] * (th'[d] + sum th'[s]); weight-free. One node per warp
// (degree-uniform: no intra-warp divergence). 16-edge groups: 4 int4 index
// loads then 16 independent row-gathers in flight (MLP 16).
__global__ __launch_bounds__(256) void k_aggregate(const float* __restrict__ b,
                                                   int layer) {
    int tid = threadIdx.x;
    int wid = tid >> 5;
    int lane = tid & 31;
    int node0 = (blockIdx.x * 8 + wid) * NPW;

    __shared__ float sh_s[64], sh_q[64];
    if (tid < 64) { sh_s[tid] = 0.0f; sh_q[tid] = 0.0f; }

    float bx = __ldg(b + lane * 2);
    float by = __ldg(b + lane * 2 + 1);
    float2 ssum = make_float2(0.f, 0.f);
    float2 ssq  = make_float2(0.f, 0.f);

    const __half2* t2 = (const __half2*)d_th;

#pragma unroll 1
    for (int n = 0; n < NPW; n++) {
        int node = node0 + n;
        if (node >= N_NODES) break;
        int cnt = d_pos[node];
        float dv = rsqrtf((float)(cnt + 1));
        const int4* bkt4 = (const int4*)&d_csr_i[node * CAP];

        float2 a0 = __half22float2(t2[node * 32 + lane]);   // self (th'[d])
        float2 a1 = make_float2(0.f, 0.f);
        float2 a2 = make_float2(0.f, 0.f);
        float2 a3 = make_float2(0.f, 0.f);

        int j = 0;
        // 16-edge groups: 4 int4 index loads, 16 independent gathers (MLP 16)
        for (; j + 16 <= cnt; j += 16) {
            int4 ia = __ldg(bkt4 + (j >> 2));
            int4 ib = __ldg(bkt4 + (j >> 2) + 1);
            int4 ic = __ldg(bkt4 + (j >> 2) + 2);
            int4 id = __ldg(bkt4 + (j >> 2) + 3);
            float2 v0 = __half22float2(t2[ia.x * 32 + lane]);
            float2 v1 = __half22float2(t2[ia.y * 32 + lane]);
            float2 v2 = __half22float2(t2[ia.z * 32 + lane]);
            float2 v3 = __half22float2(t2[ia.w * 32 + lane]);
            float2 v4 = __half22float2(t2[ib.x * 32 + lane]);
            float2 v5 = __half22float2(t2[ib.y * 32 + lane]);
            float2 v6 = __half22float2(t2[ib.z * 32 + lane]);
            float2 v7 = __half22float2(t2[ib.w * 32 + lane]);
            float2 v8 = __half22float2(t2[ic.x * 32 + lane]);
            float2 v9 = __half22float2(t2[ic.y * 32 + lane]);
            float2 va = __half22float2(t2[ic.z * 32 + lane]);
            float2 vb = __half22float2(t2[ic.w * 32 + lane]);
            float2 vc = __half22float2(t2[id.x * 32 + lane]);
            float2 vd = __half22float2(t2[id.y * 32 + lane]);
            float2 ve = __half22float2(t2[id.z * 32 + lane]);
            float2 vf = __half22float2(t2[id.w * 32 + lane]);
            a0.x += (v0.x + v4.x) + (v8.x + vc.x);
            a0.y += (v0.y + v4.y) + (v8.y + vc.y);
            a1.x += (v1.x + v5.x) + (v9.x + vd.x);
            a1.y += (v1.y + v5.y) + (v9.y + vd.y);
            a2.x += (v2.x + v6.x) + (va.x + ve.x);
            a2.y += (v2.y + v6.y) + (va.y + ve.y);
            a3.x += (v3.x + v7.x) + (vb.x + vf.x);
            a3.y += (v3.y + v7.y) + (vb.y + vf.y);
        }
        // 8-edge group
        if (j + 8 <= cnt) {
            int4 ia = __ldg(bkt4 + (j >> 2));
            int4 ib = __ldg(bkt4 + (j >> 2) + 1);
            float2 v0 = __half22float2(t2[ia.x * 32 + lane]);
            float2 v1 = __half22float2(t2[ia.y * 32 + lane]);
            float2 v2 = __half22float2(t2[ia.z * 32 + lane]);
            float2 v3 = __half22float2(t2[ia.w * 32 + lane]);
            float2 v4 = __half22float2(t2[ib.x * 32 + lane]);
            float2 v5 = __half22float2(t2[ib.y * 32 + lane]);
            float2 v6 = __half22float2(t2[ib.z * 32 + lane]);
            float2 v7 = __half22float2(t2[ib.w * 32 + lane]);
            a0.x += v0.x + v4.x; a0.y += v0.y + v4.y;
            a1.x += v1.x + v5.x; a1.y += v1.y + v5.y;
            a2.x += v2.x + v6.x; a2.y += v2.y + v6.y;
            a3.x += v3.x + v7.x; a3.y += v3.y + v7.y;
            j += 8;
        }
        // 4-edge group
        if (j + 4 <= cnt) {
            int4 ia = __ldg(bkt4 + (j >> 2));
            float2 v0 = __half22float2(t2[ia.x * 32 + lane]);
            float2 v1 = __half22float2(t2[ia.y * 32 + lane]);
            float2 v2 = __half22float2(t2[ia.z * 32 + lane]);
            float2 v3 = __half22float2(t2[ia.w * 32 + lane]);
            a0.x += v0.x; a0.y += v0.y;
            a1.x += v1.x; a1.y += v1.y;
            a2.x += v2.x; a2.y += v2.y;
            a3.x += v3.x; a3.y += v3.y;
            j += 4;
        }
        // tail (<4): one int4 load covers it (bucket slack is within CAP)
        if (j < cnt) {
            int4 ia = __ldg(bkt4 + (j >> 2));
            int rem = cnt - j;
            float2 v0 = __half22float2(t2[ia.x * 32 + lane]);
            a0.x += v0.x; a0.y += v0.y;
            if (rem > 1) {
                float2 v1 = __half22float2(t2[ia.y * 32 + lane]);
                a1.x += v1.x; a1.y += v1.y;
            }
            if (rem > 2) {
                float2 v2 = __half22float2(t2[ia.z * 32 + lane]);
                a2.x += v2.x; a2.y += v2.y;
            }
        }
        float2 acc;
        acc.x = dv * ((a0.x + a1.x) + (a2.x + a3.x));
        acc.y = dv * ((a0.y + a1.y) + (a2.y + a3.y));

        ((__half2*)d_agg)[node * 32 + lane] = __floats2half2_rn(acc.x, acc.y);

        float vx = acc.x + bx, vy = acc.y + by;
        ssum.x += vx; ssum.y += vy;
        ssq.x  += vx * vx; ssq.y += vy * vy;
    }

    __syncthreads();
    atomicAdd(&sh_s[lane * 2], ssum.x);
    atomicAdd(&sh_s[lane * 2 + 1], ssum.y);
    atomicAdd(&sh_q[lane * 2], ssq.x);
    atomicAdd(&sh_q[lane * 2 + 1], ssq.y);
    __syncthreads();
    if (tid < 64) {
        atomicAdd(&d_sumA[layer * 64 + tid], sh_s[tid]);
        atomicAdd(&d_sqA[layer * 64 + tid], sh_q[tid]);
    }
}

// ---------------- pooling (fused BN+ReLU of layer 3) + classifier -------------
// Also resets d_pos to 0 for the NEXT call.
__global__ __launch_bounds__(256) void k_pool(const int* __restrict__ batch,
                                              const float* __restrict__ gp,
                                              const float* __restrict__ bep,
                                              const float* __restrict__ bp) {
    __shared__ __align__(16) float sh_a[64], sh_c[64];
    int tid = threadIdx.x;
    if (tid < 64) {
        int o = 2 * 64 + tid;
        float mu  = d_sumA[o] * (1.0f / N_NODES);
        float var = d_sqA[o] * (1.0f / N_NODES) - mu * mu;
        float inv = rsqrtf(var + BN_EPS);
        float a = __ldg(gp + tid) * inv;
        sh_a[tid] = a;
        sh_c[tid] = __ldg(bep + tid) + a * (__ldg(bp + tid) - mu);
    }
    __syncthreads();

    int i = blockIdx.x * blockDim.x + tid;   // N*16 chunks (4 cols each)
    if (i >= N_NODES * 16) return;
    int node = i >> 4, c = i & 15;
    int g = __ldg(batch + node);
    float4 a4 = *(const float4*)&sh_a[c * 4];
    float4 c4 = *(const float4*)&sh_c[c * 4];
    uint2 pk = ((const uint2*)d_agg)[i];
    float2 lo = __half22float2(*(__half2*)&pk.x);
    float2 hi = __half22float2(*(__half2*)&pk.y);
    float4 v = make_float4(lo.x, lo.y, hi.x, hi.y);
    v.x = fmaxf(0.0f, fmaf(v.x, a4.x, c4.x));
    v.y = fmaxf(0.0f, fmaf(v.y, a4.y, c4.y));
    v.z = fmaxf(0.0f, fmaf(v.z, a4.z, c4.z));
    v.w = fmaxf(0.0f, fmaf(v.w, a4.w, c4.w));
    float* p = d_pool + (g * 64 + c * 4);
    asm volatile("red.global.add.v4.f32 [%0], {%1,%2,%3,%4};"
                 :: "l"(p), "f"(v.x), "f"(v.y), "f"(v.z), "f"(v.w)
                 : "memory");
    if (c == 0) {
        atomicAdd(&d_gcnt[g], 1.0f);
        d_pos[node] = 0;                 // reset cursor for next execution
    }
}

// fc; also zeroes pool/gcnt/BN stats for the next execution.
__global__ __launch_bounds__(64) void k_fc(const float* __restrict__ fcW,
                                           const float* __restrict__ fcb,
                                           float* __restrict__ out) {
    int g = blockIdx.x;
    int tid = threadIdx.x;  // 64
    __shared__ float p[64];
    float cnt = fmaxf(d_gcnt[g], 1.0f);
    p[tid] = d_pool[g * 64 + tid] / cnt;
    __syncthreads();

    d_pool[g * 64 + tid] = 0.0f;
    if (tid == 0) d_gcnt[g] = 0.0f;
    if (g == 0) {
#pragma unroll
        for (int l = 0; l < 3; l++) {
            d_sumA[l * 64 + tid] = 0.0f;
            d_sqA[l * 64 + tid] = 0.0f;
        }
    }

    if (tid < NCLS) {
        float acc = __ldg(fcb + tid);
#pragma unroll
        for (int k = 0; k < 64; k++)
            acc = fmaf(p[k], __ldg(fcW + k * NCLS + tid), acc);
        out[g * NCLS + tid] = acc;
    }
}

// ---------------- launch ------------------------------------------------------
extern "C" void kernel_launch(void* const* d_in, const int* in_sizes, int n_in,
                              void* d_out, int out_size) {
    const float* x     = (const float*)d_in[0];
    const int*   ei    = (const int*)d_in[1];
    const int*   src   = ei;              // edge_index[0]
    const int*   dst   = ei + N_EDGES;    // edge_index[1]
    const int*   batch = (const int*)d_in[2];
    const float* W[3]  = { (const float*)d_in[3],  (const float*)d_in[7],  (const float*)d_in[11] };
    const float* b[3]  = { (const float*)d_in[4],  (const float*)d_in[8],  (const float*)d_in[12] };
    const float* g[3]  = { (const float*)d_in[5],  (const float*)d_in[9],  (const float*)d_in[13] };
    const float* be[3] = { (const float*)d_in[6],  (const float*)d_in[10], (const float*)d_in[14] };
    const float* fcW   = (const float*)d_in[15];
    const float* fcb   = (const float*)d_in[16];
    float* out = (float*)d_out;

    const int gemm_grid = (N_NODES + 63) / 64;
    const int agg_grid = (N_NODES + 8 * NPW - 1) / (8 * NPW);

    // bucket CSR build (d_pos arrives zeroed: .bss / prev pool)
    k_scatter<<<(N_EDGES / 4 + 255) / 256, 256>>>(src, dst);

    for (int l = 0; l < 3; l++) {
        const float* gp  = l > 0 ? g[l - 1]  : g[0];
        const float* bep = l > 0 ? be[l - 1] : be[0];
        const float* bp  = l > 0 ? b[l - 1]  : b[0];
        k_gemm<<<gemm_grid, 256>>>(x, W[l], gp, bep, bp, l);
        k_aggregate<<<agg_grid, 256>>>(b[l], l);
    }

    k_pool<<<(N_NODES * 16 + 255) / 256, 256>>>(batch, g[2], be[2], b[2]);
    k_fc<<<NGRAPH, 64>>>(fcW, fcb, out);
}

// round 16
// speedup vs baseline: 1.7123x; 1.2443x over previous
#include <cuda_runtime.h>
#include <cuda_fp16.h>

#define N_NODES 50000
#define N_EDGES 800000
#define HDIM    64
#define NCLS    6
#define NGRAPH  500
#define BN_EPS  1e-5f
#define CAP     64   // per-node edge bucket capacity (max in-degree ~45)
#define NPW     8    // nodes per warp in aggregation

// ---------------- scratch (allocation-free: __device__ globals) -------------
// Cross-call state returns to zero by the END of each call (pool/fc);
// first call rides .bss zero-init.
__device__ __align__(16) __half d_th[N_NODES * HDIM];   // dinv-scaled post-GEMM features (fp16)
__device__ __align__(16) __half d_agg[N_NODES * HDIM];  // aggregated features (fp16)
__device__ int   d_pos[N_NODES];              // bucket cursors == in-degree counts
__device__ __align__(16) int d_csr_i[N_NODES * CAP];  // per-node src-index buckets
__device__ float d_sumA[3 * HDIM];            // per-layer BN sum
__device__ float d_sqA[3 * HDIM];             // per-layer BN sumsq
__device__ __align__(16) float d_pool[NGRAPH * HDIM];
__device__ float d_gcnt[NGRAPH];

// ---------------- bucket scatter ------------------------------------------------
__global__ void k_scatter(const int* __restrict__ src, const int* __restrict__ dst) {
    int e = (blockIdx.x * blockDim.x + threadIdx.x) * 4;
    if (e >= N_EDGES) return;
    int4 s4 = *(const int4*)(src + e);
    int4 d4 = *(const int4*)(dst + e);
    int p0 = atomicAdd(&d_pos[d4.x], 1);
    int p1 = atomicAdd(&d_pos[d4.y], 1);
    int p2 = atomicAdd(&d_pos[d4.z], 1);
    int p3 = atomicAdd(&d_pos[d4.w], 1);
    if (p0 < CAP) d_csr_i[d4.x * CAP + p0] = s4.x;
    if (p1 < CAP) d_csr_i[d4.y * CAP + p1] = s4.y;
    if (p2 < CAP) d_csr_i[d4.z * CAP + p2] = s4.z;
    if (p3 < CAP) d_csr_i[d4.w * CAP + p3] = s4.w;
}

// ---------------- tensor-core GEMM ---------------------------------------------
// th'[row] = dinv[row] * (act(X)[row] @ W), fp16 store.
// Restructured for latency overlap: X global loads issued FIRST into registers,
// overlapped with W staging and per-thread BN-affine computation (broadcast
// L1 hits). Single __syncthreads before the MMA phase.
__global__ __launch_bounds__(256) void k_gemm(const float* __restrict__ Xext,
                                              const float* __restrict__ W,
                                              const float* __restrict__ gp,
                                              const float* __restrict__ bep,
                                              const float* __restrict__ bp,
                                              int layer) {
    __shared__ __half Xs[64][72];    // 144B row stride: conflict-free ldmatrix
    __shared__ __half Wsh[64][72];

    const int apply_bn = layer > 0;
    int tid = threadIdx.x;
    int base = blockIdx.x * 64;
    int rl = tid >> 4, cg = tid & 15;

    // 1) issue X loads immediately (long-latency; overlapped with everything below)
    float4 xf[4];
    uint2  xh[4];
    bool okr[4];
#pragma unroll
    for (int i = 0; i < 4; i++) {
        int row = base + rl + i * 16;
        okr[i] = row < N_NODES;
        if (apply_bn) {
            xh[i] = okr[i] ? __ldg(&((const uint2*)d_agg)[row * 16 + cg])
                           : make_uint2(0u, 0u);
        } else {
            xf[i] = okr[i] ? __ldg(&((const float4*)Xext)[row * 16 + cg])
                           : make_float4(0.f, 0.f, 0.f, 0.f);
        }
    }

    // 2) stage W[k][n] -> fp16 shared (independent loads, overlap with X)
    {
        int k = tid >> 4;
#pragma unroll
        for (int i = 0; i < 4; i++) {
            float4 w = __ldg(&((const float4*)W)[(k + i * 16) * 16 + cg]);
            __half2 h0 = __floats2half2_rn(w.x, w.y);
            __half2 h1 = __floats2half2_rn(w.z, w.w);
            uint2 pk;
            pk.x = *(unsigned int*)&h0;
            pk.y = *(unsigned int*)&h1;
            *(uint2*)&Wsh[k + i * 16][cg * 4] = pk;
        }
    }

    // 3) per-thread BN-affine for this thread's 4 channels (broadcast L1 hits)
    float4 a4 = make_float4(0.f, 0.f, 0.f, 0.f);
    float4 c4 = make_float4(0.f, 0.f, 0.f, 0.f);
    if (apply_bn) {
        int ob = (layer - 1) * 64 + cg * 4;
#pragma unroll
        for (int ch = 0; ch < 4; ch++) {
            float mu  = d_sumA[ob + ch] * (1.0f / N_NODES);
            float var = d_sqA[ob + ch] * (1.0f / N_NODES) - mu * mu;
            float inv = rsqrtf(var + BN_EPS);
            float a = __ldg(gp + cg * 4 + ch) * inv;
            float c = __ldg(bep + cg * 4 + ch) + a * (__ldg(bp + cg * 4 + ch) - mu);
            ((float*)&a4)[ch] = a;
            ((float*)&c4)[ch] = c;
        }
    }

    // 4) apply + convert + store X tile
#pragma unroll
    for (int i = 0; i < 4; i++) {
        float4 v;
        if (apply_bn) {
            float2 lo = __half22float2(*(__half2*)&xh[i].x);
            float2 hi = __half22float2(*(__half2*)&xh[i].y);
            v = make_float4(lo.x, lo.y, hi.x, hi.y);
            v.x = fmaxf(0.0f, fmaf(v.x, a4.x, c4.x));
            v.y = fmaxf(0.0f, fmaf(v.y, a4.y, c4.y));
            v.z = fmaxf(0.0f, fmaf(v.z, a4.z, c4.z));
            v.w = fmaxf(0.0f, fmaf(v.w, a4.w, c4.w));
        } else {
            v = xf[i];
        }
        __half2 h0 = __floats2half2_rn(v.x, v.y);
        __half2 h1 = __floats2half2_rn(v.z, v.w);
        uint2 pk;
        pk.x = *(unsigned int*)&h0;
        pk.y = *(unsigned int*)&h1;
        *(uint2*)&Xs[rl + i * 16][cg * 4] = pk;
    }
    __syncthreads();

    int w = tid >> 5, lane = tid & 31;
    int row0 = (w & 3) * 16;      // row strip
    int ncol0 = (w >> 2) * 32;    // column half

    float c[4][4];
#pragma unroll
    for (int n = 0; n < 4; n++)
#pragma unroll
        for (int j = 0; j < 4; j++) c[n][j] = 0.0f;

#pragma unroll
    for (int kc = 0; kc < 4; kc++) {
        unsigned int a0, a1, a2, a3;
        {
            const __half* p = &Xs[row0 + (lane & 15)][kc * 16 + (lane >> 4) * 8];
            unsigned int addr = (unsigned int)__cvta_generic_to_shared(p);
            asm volatile("ldmatrix.sync.aligned.m8n8.x4.shared.b16 {%0,%1,%2,%3}, [%4];"
                         : "=r"(a0), "=r"(a1), "=r"(a2), "=r"(a3) : "r"(addr));
        }
#pragma unroll
        for (int np = 0; np < 2; np++) {
            unsigned int b0, b1, b2, b3;
            const __half* p = &Wsh[kc * 16 + (lane & 15)][ncol0 + np * 16 + (lane >> 4) * 8];
            unsigned int addr = (unsigned int)__cvta_generic_to_shared(p);
            asm volatile("ldmatrix.sync.aligned.m8n8.x4.trans.shared.b16 {%0,%1,%2,%3}, [%4];"
                         : "=r"(b0), "=r"(b1), "=r"(b2), "=r"(b3) : "r"(addr));
            int nt0 = np * 2, nt1 = np * 2 + 1;
            asm volatile("mma.sync.aligned.m16n8k16.row.col.f32.f16.f16.f32 "
                         "{%0,%1,%2,%3}, {%4,%5,%6,%7}, {%8,%9}, {%0,%1,%2,%3};"
                         : "+f"(c[nt0][0]), "+f"(c[nt0][1]), "+f"(c[nt0][2]), "+f"(c[nt0][3])
                         : "r"(a0), "r"(a1), "r"(a2), "r"(a3), "r"(b0), "r"(b1));
            asm volatile("mma.sync.aligned.m16n8k16.row.col.f32.f16.f16.f32 "
                         "{%0,%1,%2,%3}, {%4,%5,%6,%7}, {%8,%9}, {%0,%1,%2,%3};"
                         : "+f"(c[nt1][0]), "+f"(c[nt1][1]), "+f"(c[nt1][2]), "+f"(c[nt1][3])
                         : "r"(a0), "r"(a1), "r"(a2), "r"(a3), "r"(b2), "r"(b3));
        }
    }

    // epilogue: scale rows by dinv = rsqrt(deg+1), convert to fp16, store
    int r0 = base + row0 + (lane >> 2);
    int r1 = r0 + 8;
    bool ok0 = r0 < N_NODES, ok1 = r1 < N_NODES;
    float dv0 = ok0 ? rsqrtf((float)d_pos[r0] + 1.0f) : 0.0f;
    float dv1 = ok1 ? rsqrtf((float)d_pos[r1] + 1.0f) : 0.0f;
#pragma unroll
    for (int nt = 0; nt < 4; nt++) {
        int col = ncol0 + nt * 8 + (lane & 3) * 2;
        if (ok0) {
            __half2 h = __floats2half2_rn(c[nt][0] * dv0, c[nt][1] * dv0);
            *(__half2*)&d_th[r0 * 64 + col] = h;
        }
        if (ok1) {
            __half2 h = __floats2half2_rn(c[nt][2] * dv1, c[nt][3] * dv1);
            *(__half2*)&d_th[r1 * 64 + col] = h;
        }
    }
}

// ---------------- bucket pull aggregation + fused BN stats ---------------------
// agg[d] = dinv[d] * (th'[d] + sum th'[s]); weight-free. (R13 structure —
// empirically optimal: 8-edge groups, one node per warp.)
__global__ __launch_bounds__(256) void k_aggregate(const float* __restrict__ b,
                                                   int layer) {
    int tid = threadIdx.x;
    int wid = tid >> 5;
    int lane = tid & 31;
    int node0 = (blockIdx.x * 8 + wid) * NPW;

    __shared__ float sh_s[64], sh_q[64];
    if (tid < 64) { sh_s[tid] = 0.0f; sh_q[tid] = 0.0f; }

    float bx = __ldg(b + lane * 2);
    float by = __ldg(b + lane * 2 + 1);
    float2 ssum = make_float2(0.f, 0.f);
    float2 ssq  = make_float2(0.f, 0.f);

    const __half2* t2 = (const __half2*)d_th;

#pragma unroll 1
    for (int n = 0; n < NPW; n++) {
        int node = node0 + n;
        if (node >= N_NODES) break;
        int cnt = d_pos[node];
        float dv = rsqrtf((float)(cnt + 1));
        const int4* bkt4 = (const int4*)&d_csr_i[node * CAP];

        float2 a0 = __half22float2(t2[node * 32 + lane]);   // self (th'[d])
        float2 a1 = make_float2(0.f, 0.f);
        float2 a2 = make_float2(0.f, 0.f);
        float2 a3 = make_float2(0.f, 0.f);

        int j = 0;
        // 8-edge groups: 2 int4 index loads, 8 independent gathers (MLP 8)
        for (; j + 8 <= cnt; j += 8) {
            int4 ia = __ldg(bkt4 + (j >> 2));
            int4 ib = __ldg(bkt4 + (j >> 2) + 1);
            float2 v0 = __half22float2(t2[ia.x * 32 + lane]);
            float2 v1 = __half22float2(t2[ia.y * 32 + lane]);
            float2 v2 = __half22float2(t2[ia.z * 32 + lane]);
            float2 v3 = __half22float2(t2[ia.w * 32 + lane]);
            float2 v4 = __half22float2(t2[ib.x * 32 + lane]);
            float2 v5 = __half22float2(t2[ib.y * 32 + lane]);
            float2 v6 = __half22float2(t2[ib.z * 32 + lane]);
            float2 v7 = __half22float2(t2[ib.w * 32 + lane]);
            a0.x += v0.x + v4.x; a0.y += v0.y + v4.y;
            a1.x += v1.x + v5.x; a1.y += v1.y + v5.y;
            a2.x += v2.x + v6.x; a2.y += v2.y + v6.y;
            a3.x += v3.x + v7.x; a3.y += v3.y + v7.y;
        }
        // 4-edge group
        if (j + 4 <= cnt) {
            int4 ia = __ldg(bkt4 + (j >> 2));
            float2 v0 = __half22float2(t2[ia.x * 32 + lane]);
            float2 v1 = __half22float2(t2[ia.y * 32 + lane]);
            float2 v2 = __half22float2(t2[ia.z * 32 + lane]);
            float2 v3 = __half22float2(t2[ia.w * 32 + lane]);
            a0.x += v0.x; a0.y += v0.y;
            a1.x += v1.x; a1.y += v1.y;
            a2.x += v2.x; a2.y += v2.y;
            a3.x += v3.x; a3.y += v3.y;
            j += 4;
        }
        // tail (<4): one int4 load covers it (bucket slack is within CAP)
        if (j < cnt) {
            int4 ia = __ldg(bkt4 + (j >> 2));
            int rem = cnt - j;
            float2 v0 = __half22float2(t2[ia.x * 32 + lane]);
            a0.x += v0.x; a0.y += v0.y;
            if (rem > 1) {
                float2 v1 = __half22float2(t2[ia.y * 32 + lane]);
                a1.x += v1.x; a1.y += v1.y;
            }
            if (rem > 2) {
                float2 v2 = __half22float2(t2[ia.z * 32 + lane]);
                a2.x += v2.x; a2.y += v2.y;
            }
        }
        float2 acc;
        acc.x = dv * ((a0.x + a1.x) + (a2.x + a3.x));
        acc.y = dv * ((a0.y + a1.y) + (a2.y + a3.y));

        ((__half2*)d_agg)[node * 32 + lane] = __floats2half2_rn(acc.x, acc.y);

        float vx = acc.x + bx, vy = acc.y + by;
        ssum.x += vx; ssum.y += vy;
        ssq.x  += vx * vx; ssq.y += vy * vy;
    }

    __syncthreads();
    atomicAdd(&sh_s[lane * 2], ssum.x);
    atomicAdd(&sh_s[lane * 2 + 1], ssum.y);
    atomicAdd(&sh_q[lane * 2], ssq.x);
    atomicAdd(&sh_q[lane * 2 + 1], ssq.y);
    __syncthreads();
    if (tid < 64) {
        atomicAdd(&d_sumA[layer * 64 + tid], sh_s[tid]);
        atomicAdd(&d_sqA[layer * 64 + tid], sh_q[tid]);
    }
}

// ---------------- pooling (fused BN+ReLU of layer 3) + classifier -------------
// Also resets d_pos to 0 for the NEXT call.
__global__ __launch_bounds__(256) void k_pool(const int* __restrict__ batch,
                                              const float* __restrict__ gp,
                                              const float* __restrict__ bep,
                                              const float* __restrict__ bp) {
    __shared__ __align__(16) float sh_a[64], sh_c[64];
    int tid = threadIdx.x;
    if (tid < 64) {
        int o = 2 * 64 + tid;
        float mu  = d_sumA[o] * (1.0f / N_NODES);
        float var = d_sqA[o] * (1.0f / N_NODES) - mu * mu;
        float inv = rsqrtf(var + BN_EPS);
        float a = __ldg(gp + tid) * inv;
        sh_a[tid] = a;
        sh_c[tid] = __ldg(bep + tid) + a * (__ldg(bp + tid) - mu);
    }
    __syncthreads();

    int i = blockIdx.x * blockDim.x + tid;   // N*16 chunks (4 cols each)
    if (i >= N_NODES * 16) return;
    int node = i >> 4, c = i & 15;
    int g = __ldg(batch + node);
    float4 a4 = *(const float4*)&sh_a[c * 4];
    float4 c4 = *(const float4*)&sh_c[c * 4];
    uint2 pk = ((const uint2*)d_agg)[i];
    float2 lo = __half22float2(*(__half2*)&pk.x);
    float2 hi = __half22float2(*(__half2*)&pk.y);
    float4 v = make_float4(lo.x, lo.y, hi.x, hi.y);
    v.x = fmaxf(0.0f, fmaf(v.x, a4.x, c4.x));
    v.y = fmaxf(0.0f, fmaf(v.y, a4.y, c4.y));
    v.z = fmaxf(0.0f, fmaf(v.z, a4.z, c4.z));
    v.w = fmaxf(0.0f, fmaf(v.w, a4.w, c4.w));
    float* p = d_pool + (g * 64 + c * 4);
    asm volatile("red.global.add.v4.f32 [%0], {%1,%2,%3,%4};"
                 :: "l"(p), "f"(v.x), "f"(v.y), "f"(v.z), "f"(v.w)
                 : "memory");
    if (c == 0) {
        atomicAdd(&d_gcnt[g], 1.0f);
        d_pos[node] = 0;                 // reset cursor for next execution
    }
}

// fc; also zeroes pool/gcnt/BN stats for the next execution.
__global__ __launch_bounds__(64) void k_fc(const float* __restrict__ fcW,
                                           const float* __restrict__ fcb,
                                           float* __restrict__ out) {
    int g = blockIdx.x;
    int tid = threadIdx.x;  // 64
    __shared__ float p[64];
    float cnt = fmaxf(d_gcnt[g], 1.0f);
    p[tid] = d_pool[g * 64 + tid] / cnt;
    __syncthreads();

    d_pool[g * 64 + tid] = 0.0f;
    if (tid == 0) d_gcnt[g] = 0.0f;
    if (g == 0) {
#pragma unroll
        for (int l = 0; l < 3; l++) {
            d_sumA[l * 64 + tid] = 0.0f;
            d_sqA[l * 64 + tid] = 0.0f;
        }
    }

    if (tid < NCLS) {
        float acc = __ldg(fcb + tid);
#pragma unroll
        for (int k = 0; k < 64; k++)
            acc = fmaf(p[k], __ldg(fcW + k * NCLS + tid), acc);
        out[g * NCLS + tid] = acc;
    }
}

// ---------------- launch ------------------------------------------------------
extern "C" void kernel_launch(void* const* d_in, const int* in_sizes, int n_in,
                              void* d_out, int out_size) {
    const float* x     = (const float*)d_in[0];
    const int*   ei    = (const int*)d_in[1];
    const int*   src   = ei;              // edge_index[0]
    const int*   dst   = ei + N_EDGES;    // edge_index[1]
    const int*   batch = (const int*)d_in[2];
    const float* W[3]  = { (const float*)d_in[3],  (const float*)d_in[7],  (const float*)d_in[11] };
    const float* b[3]  = { (const float*)d_in[4],  (const float*)d_in[8],  (const float*)d_in[12] };
    const float* g[3]  = { (const float*)d_in[5],  (const float*)d_in[9],  (const float*)d_in[13] };
    const float* be[3] = { (const float*)d_in[6],  (const float*)d_in[10], (const float*)d_in[14] };
    const float* fcW   = (const float*)d_in[15];
    const float* fcb   = (const float*)d_in[16];
    float* out = (float*)d_out;

    const int gemm_grid = (N_NODES + 63) / 64;
    const int agg_grid = (N_NODES + 8 * NPW - 1) / (8 * NPW);

    // bucket CSR build (d_pos arrives zeroed: .bss / prev pool)
    k_scatter<<<(N_EDGES / 4 + 255) / 256, 256>>>(src, dst);

    for (int l = 0; l < 3; l++) {
        const float* gp  = l > 0 ? g[l - 1]  : g[0];
        const float* bep = l > 0 ? be[l - 1] : be[0];
        const float* bp  = l > 0 ? b[l - 1]  : b[0];
        k_gemm<<<gemm_grid, 256>>>(x, W[l], gp, bep, bp, l);
        k_aggregate<<<agg_grid, 256>>>(b[l], l);
    }

    k_pool<<<(N_NODES * 16 + 255) / 256, 256>>>(batch, g[2], be[2], b[2]);
    k_fc<<<NGRAPH, 64>>>(fcW, fcb, out);
}

// round 17
// speedup vs baseline: 1.7643x; 1.0304x over previous
#include <cuda_runtime.h>
#include <cuda_fp16.h>

#define N_NODES 50000
#define N_EDGES 800000
#define HDIM    64
#define NCLS    6
#define NGRAPH  500
#define BN_EPS  1e-5f
#define CAP     64   // per-node edge bucket capacity (max in-degree ~45)
#define NPW     8    // nodes per warp in aggregation

// ---------------- scratch (allocation-free: __device__ globals) -------------
// Cross-call state returns to zero by the END of each call (pool/fc);
// first call rides .bss zero-init.
__device__ __align__(16) __half d_th[N_NODES * HDIM];   // dinv-scaled post-GEMM features (fp16)
__device__ __align__(16) __half d_agg[N_NODES * HDIM];  // aggregated features (fp16)
__device__ int   d_pos[N_NODES];              // bucket cursors == in-degree counts
__device__ __align__(16) int d_csr_i[N_NODES * CAP];  // per-node src-index buckets
__device__ float d_sumA[3 * HDIM];            // per-layer BN sum
__device__ float d_sqA[3 * HDIM];             // per-layer BN sumsq
__device__ __align__(16) float d_pool[NGRAPH * HDIM];
__device__ float d_gcnt[NGRAPH];

// ---------------- bucket scatter ------------------------------------------------
// 8 edges per thread: 2x int4 loads each of src/dst, 8 independent
// atomic->store chains (MLP 8).
__global__ void k_scatter(const int* __restrict__ src, const int* __restrict__ dst) {
    int e = (blockIdx.x * blockDim.x + threadIdx.x) * 8;
    if (e >= N_EDGES) return;
    int4 sa = *(const int4*)(src + e);
    int4 sb = *(const int4*)(src + e + 4);
    int4 da = *(const int4*)(dst + e);
    int4 db = *(const int4*)(dst + e + 4);
    int p0 = atomicAdd(&d_pos[da.x], 1);
    int p1 = atomicAdd(&d_pos[da.y], 1);
    int p2 = atomicAdd(&d_pos[da.z], 1);
    int p3 = atomicAdd(&d_pos[da.w], 1);
    int p4 = atomicAdd(&d_pos[db.x], 1);
    int p5 = atomicAdd(&d_pos[db.y], 1);
    int p6 = atomicAdd(&d_pos[db.z], 1);
    int p7 = atomicAdd(&d_pos[db.w], 1);
    if (p0 < CAP) d_csr_i[da.x * CAP + p0] = sa.x;
    if (p1 < CAP) d_csr_i[da.y * CAP + p1] = sa.y;
    if (p2 < CAP) d_csr_i[da.z * CAP + p2] = sa.z;
    if (p3 < CAP) d_csr_i[da.w * CAP + p3] = sa.w;
    if (p4 < CAP) d_csr_i[db.x * CAP + p4] = sb.x;
    if (p5 < CAP) d_csr_i[db.y * CAP + p5] = sb.y;
    if (p6 < CAP) d_csr_i[db.z * CAP + p6] = sb.z;
    if (p7 < CAP) d_csr_i[db.w * CAP + p7] = sb.w;
}

// ---------------- tensor-core GEMM (R13 form — frozen) --------------------------
// th'[row] = dinv[row] * (act(X)[row] @ W), fp16 store.
// 64-row tile, 256 threads = 8 warps: warp w -> rows (w&3)*16, cols (w>>2)*32.
__global__ __launch_bounds__(256) void k_gemm(const float* __restrict__ Xext,
                                              const float* __restrict__ W,
                                              const float* __restrict__ gp,
                                              const float* __restrict__ bep,
                                              const float* __restrict__ bp,
                                              int layer) {
    __shared__ __half Xs[64][72];    // 144B row stride: conflict-free ldmatrix
    __shared__ __half Wsh[64][72];
    __shared__ __align__(16) float sh_a[64], sh_c[64];

    const int apply_bn = layer > 0;
    int tid = threadIdx.x;
    int base = blockIdx.x * 64;

    if (apply_bn && tid < 64) {
        int o = (layer - 1) * 64 + tid;
        float mu  = d_sumA[o] * (1.0f / N_NODES);
        float var = d_sqA[o] * (1.0f / N_NODES) - mu * mu;
        float inv = rsqrtf(var + BN_EPS);
        float a = __ldg(gp + tid) * inv;
        sh_a[tid] = a;
        sh_c[tid] = __ldg(bep + tid) + a * (__ldg(bp + tid) - mu);
    }

    // stage W[k][n] -> fp16 shared
    {
        int k = tid >> 4, cg = tid & 15;
#pragma unroll
        for (int i = 0; i < 4; i++) {
            float4 w = ((const float4*)W)[(k + i * 16) * 16 + cg];
            __half2 h0 = __floats2half2_rn(w.x, w.y);
            __half2 h1 = __floats2half2_rn(w.z, w.w);
            uint2 pk;
            pk.x = *(unsigned int*)&h0;
            pk.y = *(unsigned int*)&h1;
            *(uint2*)&Wsh[k + i * 16][cg * 4] = pk;
        }
    }
    __syncthreads();  // sh_a/sh_c ready before X staging uses them

    // stage X tile -> fp16 shared (layer 0: fp32 ext; layers 1,2: fp16 d_agg + BN)
    {
        int rl = tid >> 4, cg = tid & 15;
        float4 a4 = make_float4(0.f, 0.f, 0.f, 0.f);
        float4 c4 = make_float4(0.f, 0.f, 0.f, 0.f);
        if (apply_bn) {
            a4 = *(const float4*)&sh_a[cg * 4];
            c4 = *(const float4*)&sh_c[cg * 4];
        }
#pragma unroll
        for (int i = 0; i < 4; i++) {
            int row = base + rl + i * 16;
            float4 v = make_float4(0.f, 0.f, 0.f, 0.f);
            if (row < N_NODES) {
                if (apply_bn) {
                    uint2 pk = ((const uint2*)d_agg)[row * 16 + cg];
                    float2 lo = __half22float2(*(__half2*)&pk.x);
                    float2 hi = __half22float2(*(__half2*)&pk.y);
                    v = make_float4(lo.x, lo.y, hi.x, hi.y);
                    v.x = fmaxf(0.0f, fmaf(v.x, a4.x, c4.x));
                    v.y = fmaxf(0.0f, fmaf(v.y, a4.y, c4.y));
                    v.z = fmaxf(0.0f, fmaf(v.z, a4.z, c4.z));
                    v.w = fmaxf(0.0f, fmaf(v.w, a4.w, c4.w));
                } else {
                    v = ((const float4*)Xext)[row * 16 + cg];
                }
            }
            __half2 h0 = __floats2half2_rn(v.x, v.y);
            __half2 h1 = __floats2half2_rn(v.z, v.w);
            uint2 pk;
            pk.x = *(unsigned int*)&h0;
            pk.y = *(unsigned int*)&h1;
            *(uint2*)&Xs[rl + i * 16][cg * 4] = pk;
        }
    }
    __syncthreads();

    int w = tid >> 5, lane = tid & 31;
    int row0 = (w & 3) * 16;      // row strip
    int ncol0 = (w >> 2) * 32;    // column half

    float c[4][4];
#pragma unroll
    for (int n = 0; n < 4; n++)
#pragma unroll
        for (int j = 0; j < 4; j++) c[n][j] = 0.0f;

#pragma unroll
    for (int kc = 0; kc < 4; kc++) {
        unsigned int a0, a1, a2, a3;
        {
            const __half* p = &Xs[row0 + (lane & 15)][kc * 16 + (lane >> 4) * 8];
            unsigned int addr = (unsigned int)__cvta_generic_to_shared(p);
            asm volatile("ldmatrix.sync.aligned.m8n8.x4.shared.b16 {%0,%1,%2,%3}, [%4];"
                         : "=r"(a0), "=r"(a1), "=r"(a2), "=r"(a3) : "r"(addr));
        }
#pragma unroll
        for (int np = 0; np < 2; np++) {
            unsigned int b0, b1, b2, b3;
            const __half* p = &Wsh[kc * 16 + (lane & 15)][ncol0 + np * 16 + (lane >> 4) * 8];
            unsigned int addr = (unsigned int)__cvta_generic_to_shared(p);
            asm volatile("ldmatrix.sync.aligned.m8n8.x4.trans.shared.b16 {%0,%1,%2,%3}, [%4];"
                         : "=r"(b0), "=r"(b1), "=r"(b2), "=r"(b3) : "r"(addr));
            int nt0 = np * 2, nt1 = np * 2 + 1;
            asm volatile("mma.sync.aligned.m16n8k16.row.col.f32.f16.f16.f32 "
                         "{%0,%1,%2,%3}, {%4,%5,%6,%7}, {%8,%9}, {%0,%1,%2,%3};"
                         : "+f"(c[nt0][0]), "+f"(c[nt0][1]), "+f"(c[nt0][2]), "+f"(c[nt0][3])
                         : "r"(a0), "r"(a1), "r"(a2), "r"(a3), "r"(b0), "r"(b1));
            asm volatile("mma.sync.aligned.m16n8k16.row.col.f32.f16.f16.f32 "
                         "{%0,%1,%2,%3}, {%4,%5,%6,%7}, {%8,%9}, {%0,%1,%2,%3};"
                         : "+f"(c[nt1][0]), "+f"(c[nt1][1]), "+f"(c[nt1][2]), "+f"(c[nt1][3])
                         : "r"(a0), "r"(a1), "r"(a2), "r"(a3), "r"(b2), "r"(b3));
        }
    }

    // epilogue: scale rows by dinv = rsqrt(deg+1), convert to fp16, store
    int r0 = base + row0 + (lane >> 2);
    int r1 = r0 + 8;
    bool ok0 = r0 < N_NODES, ok1 = r1 < N_NODES;
    float dv0 = ok0 ? rsqrtf((float)d_pos[r0] + 1.0f) : 0.0f;
    float dv1 = ok1 ? rsqrtf((float)d_pos[r1] + 1.0f) : 0.0f;
#pragma unroll
    for (int nt = 0; nt < 4; nt++) {
        int col = ncol0 + nt * 8 + (lane & 3) * 2;
        if (ok0) {
            __half2 h = __floats2half2_rn(c[nt][0] * dv0, c[nt][1] * dv0);
            *(__half2*)&d_th[r0 * 64 + col] = h;
        }
        if (ok1) {
            __half2 h = __floats2half2_rn(c[nt][2] * dv1, c[nt][3] * dv1);
            *(__half2*)&d_th[r1 * 64 + col] = h;
        }
    }
}

// ---------------- bucket pull aggregation + fused BN stats (R13 form — frozen) --
// agg[d] = dinv[d] * (th'[d] + sum th'[s]); weight-free. One node per warp,
// 8-edge groups (empirically optimal for Poisson(16) degrees).
__global__ __launch_bounds__(256) void k_aggregate(const float* __restrict__ b,
                                                   int layer) {
    int tid = threadIdx.x;
    int wid = tid >> 5;
    int lane = tid & 31;
    int node0 = (blockIdx.x * 8 + wid) * NPW;

    __shared__ float sh_s[64], sh_q[64];
    if (tid < 64) { sh_s[tid] = 0.0f; sh_q[tid] = 0.0f; }

    float bx = __ldg(b + lane * 2);
    float by = __ldg(b + lane * 2 + 1);
    float2 ssum = make_float2(0.f, 0.f);
    float2 ssq  = make_float2(0.f, 0.f);

    const __half2* t2 = (const __half2*)d_th;

#pragma unroll 1
    for (int n = 0; n < NPW; n++) {
        int node = node0 + n;
        if (node >= N_NODES) break;
        int cnt = d_pos[node];
        float dv = rsqrtf((float)(cnt + 1));
        const int4* bkt4 = (const int4*)&d_csr_i[node * CAP];

        float2 a0 = __half22float2(t2[node * 32 + lane]);   // self (th'[d])
        float2 a1 = make_float2(0.f, 0.f);
        float2 a2 = make_float2(0.f, 0.f);
        float2 a3 = make_float2(0.f, 0.f);

        int j = 0;
        // 8-edge groups: 2 int4 index loads, 8 independent gathers (MLP 8)
        for (; j + 8 <= cnt; j += 8) {
            int4 ia = __ldg(bkt4 + (j >> 2));
            int4 ib = __ldg(bkt4 + (j >> 2) + 1);
            float2 v0 = __half22float2(t2[ia.x * 32 + lane]);
            float2 v1 = __half22float2(t2[ia.y * 32 + lane]);
            float2 v2 = __half22float2(t2[ia.z * 32 + lane]);
            float2 v3 = __half22float2(t2[ia.w * 32 + lane]);
            float2 v4 = __half22float2(t2[ib.x * 32 + lane]);
            float2 v5 = __half22float2(t2[ib.y * 32 + lane]);
            float2 v6 = __half22float2(t2[ib.z * 32 + lane]);
            float2 v7 = __half22float2(t2[ib.w * 32 + lane]);
            a0.x += v0.x + v4.x; a0.y += v0.y + v4.y;
            a1.x += v1.x + v5.x; a1.y += v1.y + v5.y;
            a2.x += v2.x + v6.x; a2.y += v2.y + v6.y;
            a3.x += v3.x + v7.x; a3.y += v3.y + v7.y;
        }
        // 4-edge group
        if (j + 4 <= cnt) {
            int4 ia = __ldg(bkt4 + (j >> 2));
            float2 v0 = __half22float2(t2[ia.x * 32 + lane]);
            float2 v1 = __half22float2(t2[ia.y * 32 + lane]);
            float2 v2 = __half22float2(t2[ia.z * 32 + lane]);
            float2 v3 = __half22float2(t2[ia.w * 32 + lane]);
            a0.x += v0.x; a0.y += v0.y;
            a1.x += v1.x; a1.y += v1.y;
            a2.x += v2.x; a2.y += v2.y;
            a3.x += v3.x; a3.y += v3.y;
            j += 4;
        }
        // tail (<4): one int4 load covers it (bucket slack is within CAP)
        if (j < cnt) {
            int4 ia = __ldg(bkt4 + (j >> 2));
            int rem = cnt - j;
            float2 v0 = __half22float2(t2[ia.x * 32 + lane]);
            a0.x += v0.x; a0.y += v0.y;
            if (rem > 1) {
                float2 v1 = __half22float2(t2[ia.y * 32 + lane]);
                a1.x += v1.x; a1.y += v1.y;
            }
            if (rem > 2) {
                float2 v2 = __half22float2(t2[ia.z * 32 + lane]);
                a2.x += v2.x; a2.y += v2.y;
            }
        }
        float2 acc;
        acc.x = dv * ((a0.x + a1.x) + (a2.x + a3.x));
        acc.y = dv * ((a0.y + a1.y) + (a2.y + a3.y));

        ((__half2*)d_agg)[node * 32 + lane] = __floats2half2_rn(acc.x, acc.y);

        float vx = acc.x + bx, vy = acc.y + by;
        ssum.x += vx; ssum.y += vy;
        ssq.x  += vx * vx; ssq.y += vy * vy;
    }

    __syncthreads();
    atomicAdd(&sh_s[lane * 2], ssum.x);
    atomicAdd(&sh_s[lane * 2 + 1], ssum.y);
    atomicAdd(&sh_q[lane * 2], ssq.x);
    atomicAdd(&sh_q[lane * 2 + 1], ssq.y);
    __syncthreads();
    if (tid < 64) {
        atomicAdd(&d_sumA[layer * 64 + tid], sh_s[tid]);
        atomicAdd(&d_sqA[layer * 64 + tid], sh_q[tid]);
    }
}

// ---------------- pooling (fused BN+ReLU of layer 3) + classifier -------------
// Also resets d_pos to 0 for the NEXT call.
__global__ __launch_bounds__(256) void k_pool(const int* __restrict__ batch,
                                              const float* __restrict__ gp,
                                              const float* __restrict__ bep,
                                              const float* __restrict__ bp) {
    __shared__ __align__(16) float sh_a[64], sh_c[64];
    int tid = threadIdx.x;
    if (tid < 64) {
        int o = 2 * 64 + tid;
        float mu  = d_sumA[o] * (1.0f / N_NODES);
        float var = d_sqA[o] * (1.0f / N_NODES) - mu * mu;
        float inv = rsqrtf(var + BN_EPS);
        float a = __ldg(gp + tid) * inv;
        sh_a[tid] = a;
        sh_c[tid] = __ldg(bep + tid) + a * (__ldg(bp + tid) - mu);
    }
    __syncthreads();

    int i = blockIdx.x * blockDim.x + tid;   // N*16 chunks (4 cols each)
    if (i >= N_NODES * 16) return;
    int node = i >> 4, c = i & 15;
    int g = __ldg(batch + node);
    float4 a4 = *(const float4*)&sh_a[c * 4];
    float4 c4 = *(const float4*)&sh_c[c * 4];
    uint2 pk = ((const uint2*)d_agg)[i];
    float2 lo = __half22float2(*(__half2*)&pk.x);
    float2 hi = __half22float2(*(__half2*)&pk.y);
    float4 v = make_float4(lo.x, lo.y, hi.x, hi.y);
    v.x = fmaxf(0.0f, fmaf(v.x, a4.x, c4.x));
    v.y = fmaxf(0.0f, fmaf(v.y, a4.y, c4.y));
    v.z = fmaxf(0.0f, fmaf(v.z, a4.z, c4.z));
    v.w = fmaxf(0.0f, fmaf(v.w, a4.w, c4.w));
    float* p = d_pool + (g * 64 + c * 4);
    asm volatile("red.global.add.v4.f32 [%0], {%1,%2,%3,%4};"
                 :: "l"(p), "f"(v.x), "f"(v.y), "f"(v.z), "f"(v.w)
                 : "memory");
    if (c == 0) {
        atomicAdd(&d_gcnt[g], 1.0f);
        d_pos[node] = 0;                 // reset cursor for next execution
    }
}

// fc; also zeroes pool/gcnt/BN stats for the next execution.
__global__ __launch_bounds__(64) void k_fc(const float* __restrict__ fcW,
                                           const float* __restrict__ fcb,
                                           float* __restrict__ out) {
    int g = blockIdx.x;
    int tid = threadIdx.x;  // 64
    __shared__ float p[64];
    float cnt = fmaxf(d_gcnt[g], 1.0f);
    p[tid] = d_pool[g * 64 + tid] / cnt;
    __syncthreads();

    d_pool[g * 64 + tid] = 0.0f;
    if (tid == 0) d_gcnt[g] = 0.0f;
    if (g == 0) {
#pragma unroll
        for (int l = 0; l < 3; l++) {
            d_sumA[l * 64 + tid] = 0.0f;
            d_sqA[l * 64 + tid] = 0.0f;
        }
    }

    if (tid < NCLS) {
        float acc = __ldg(fcb + tid);
#pragma unroll
        for (int k = 0; k < 64; k++)
            acc = fmaf(p[k], __ldg(fcW + k * NCLS + tid), acc);
        out[g * NCLS + tid] = acc;
    }
}

// ---------------- launch ------------------------------------------------------
extern "C" void kernel_launch(void* const* d_in, const int* in_sizes, int n_in,
                              void* d_out, int out_size) {
    const float* x     = (const float*)d_in[0];
    const int*   ei    = (const int*)d_in[1];
    const int*   src   = ei;              // edge_index[0]
    const int*   dst   = ei + N_EDGES;    // edge_index[1]
    const int*   batch = (const int*)d_in[2];
    const float* W[3]  = { (const float*)d_in[3],  (const float*)d_in[7],  (const float*)d_in[11] };
    const float* b[3]  = { (const float*)d_in[4],  (const float*)d_in[8],  (const float*)d_in[12] };
    const float* g[3]  = { (const float*)d_in[5],  (const float*)d_in[9],  (const float*)d_in[13] };
    const float* be[3] = { (const float*)d_in[6],  (const float*)d_in[10], (const float*)d_in[14] };
    const float* fcW   = (const float*)d_in[15];
    const float* fcb   = (const float*)d_in[16];
    float* out = (float*)d_out;

    const int gemm_grid = (N_NODES + 63) / 64;
    const int agg_grid = (N_NODES + 8 * NPW - 1) / (8 * NPW);

    // bucket CSR build (d_pos arrives zeroed: .bss / prev pool)
    k_scatter<<<(N_EDGES / 8 + 255) / 256, 256>>>(src, dst);

    for (int l = 0; l < 3; l++) {
        const float* gp  = l > 0 ? g[l - 1]  : g[0];
        const float* bep = l > 0 ? be[l - 1] : be[0];
        const float* bp  = l > 0 ? b[l - 1]  : b[0];
        k_gemm<<<gemm_grid, 256>>>(x, W[l], gp, bep, bp, l);
        k_aggregate<<<agg_grid, 256>>>(b[l], l);
    }

    k_pool<<<(N_NODES * 16 + 255) / 256, 256>>>(batch, g[2], be[2], b[2]);
    k_fc<<<NGRAPH, 64>>>(fcW, fcb, out);
}